// round 13
// baseline (speedup 1.0000x reference)
#include <cuda_runtime.h>
#include <math.h>

// Problem constants (fixed by the dataset: B=4, H=W=256, C=64, r=8)
#define HW      65536
#define CMID    64
#define RNUM    8
#define MAXB    4
#define NCH     16   // mean-reduction chunks per plane
#define NPBLK   64   // P-contraction blocks (each: one r, 8 o's)

// -------- device scratch (no allocations allowed) --------
__device__ float g_part[MAXB * 4][NCH];        // partial plane sums
__device__ float g_P  [RNUM][RNUM][CMID][4];   // P[r][i][o][j] = sum_c Wk2[r][o*C+c][i] * W1[c][j]
__device__ float g_PV [RNUM][RNUM][CMID];      // same contracted with b1
__device__ float g_Pb [RNUM][CMID][4];         // bk2 folded with W1
__device__ float g_PVb[RNUM][CMID];            // bk2 folded with b1
__device__ float g_Mt [MAXB][RNUM][4][CMID];   // final fused kernel (transposed)
__device__ float g_V  [MAXB][RNUM][CMID];      // final fused bias
__device__ float g_G[RNUM][4];                 // fused guide: Wg @ W1
__device__ float g_gb[RNUM];                   // fused guide bias

// ---------------- packed f32x2 helpers ----------------
__device__ __forceinline__ unsigned long long fma2(unsigned long long a,
                                                   unsigned long long b,
                                                   unsigned long long c)
{
    unsigned long long d;
    asm("fma.rn.f32x2 %0, %1, %2, %3;" : "=l"(d) : "l"(a), "l"(b), "l"(c));
    return d;
}
__device__ __forceinline__ unsigned long long pack2(float x)
{
    unsigned long long d;
    unsigned int u = __float_as_uint(x);
    asm("mov.b64 %0, {%1, %1};" : "=l"(d) : "r"(u));
    return d;
}
__device__ __forceinline__ void unpack2(unsigned long long v, float& lo, float& hi)
{
    unsigned int a, b;
    asm("mov.b64 {%0, %1}, %2;" : "=r"(a), "=r"(b) : "l"(v));
    lo = __uint_as_float(a);
    hi = __uint_as_float(b);
}

// =====================================================================
// Kernel A (256 threads/block): independent roles per block.
//  [0, NPBLK)           : P contraction — ALL 256 threads, conflict-free
//                         interleaved-c smem reads, 16-iteration loop.
//  [NPBLK, NPBLK+nMean) : plane-mean partial sums (NCH=16 -> 256 blocks)
//  last                 : fused guide (warp-parallel)
// =====================================================================
__global__ void __launch_bounds__(256)
k_A(const float* __restrict__ rgb,  const float* __restrict__ edge,
    const float* __restrict__ W1,   const float* __restrict__ b1,
    const float* __restrict__ Wk2,  const float* __restrict__ bk2,
    const float* __restrict__ Wg,   const float* __restrict__ bg,
    int nMean)
{
    int blk = blockIdx.x;
    int t   = threadIdx.x;

    if (blk < NPBLK) {
        // ---- P contraction: r = blk>>3, og = blk&7 (o in [og*8, og*8+8)) ----
        __shared__ float w2s[8 * CMID * 8];   // [oi][c][i] flat, 16 KB
        __shared__ float bks[8 * CMID];       // [oi][c],      2 KB
        __shared__ float w1s[CMID * 4];
        __shared__ float b1s[CMID];

        int r  = blk >> 3, og = blk & 7;

        {
            const float4* src = (const float4*)(Wk2 + (size_t)r * 32768 + og * 4096);
            float4* dst = (float4*)w2s;
            #pragma unroll
            for (int k = 0; k < 4; k++)                 // 1024 float4
                dst[k * 256 + t] = src[k * 256 + t];
            const float4* srcb = (const float4*)(bk2 + (size_t)r * 4096 + og * 512);
            if (t < 128) ((float4*)bks)[t] = srcb[t];   // 128 float4
            if (t >= 128 && t < 192) ((float4*)w1s)[t - 128] = ((const float4*)W1)[t - 128];
            if (t >= 192 && t < 208) ((float4*)b1s)[t - 192] = ((const float4*)b1)[t - 192];
        }
        __syncthreads();

        {
            // thread = (oi, i, q): q = c-quarter, c interleaved as cc*4+q
            int q  = t & 3;              // 0..3
            int i  = (t >> 2) & 7;       // 0..7
            int oi = t >> 5;             // 0..7
            int o  = og * 8 + oi;

            float p0 = 0.f, p1 = 0.f, p2 = 0.f, p3 = 0.f, p4 = 0.f;
            float q0 = 0.f, q1 = 0.f, q2 = 0.f, q3 = 0.f, q4 = 0.f;
            const bool do_b = (i == 0);
            const float* wrow = &w2s[oi * (CMID * 8) + i];
            const float* brow = &bks[oi * CMID];

            #pragma unroll
            for (int cc = 0; cc < 16; cc++) {
                int c = cc * 4 + q;      // banks 8q+i: conflict-free
                float kv = wrow[c * 8];
                float4 w = *(const float4*)(w1s + c * 4);
                float  bb = b1s[c];
                p0 += kv * w.x;  p1 += kv * w.y;  p2 += kv * w.z;  p3 += kv * w.w;
                p4 += kv * bb;
                if (do_b) {
                    float bz = brow[c];
                    q0 += bz * w.x;  q1 += bz * w.y;  q2 += bz * w.z;  q3 += bz * w.w;
                    q4 += bz * bb;
                }
            }
            #pragma unroll
            for (int off = 1; off < 4; off <<= 1) {
                p0 += __shfl_xor_sync(0xffffffffu, p0, off);
                p1 += __shfl_xor_sync(0xffffffffu, p1, off);
                p2 += __shfl_xor_sync(0xffffffffu, p2, off);
                p3 += __shfl_xor_sync(0xffffffffu, p3, off);
                p4 += __shfl_xor_sync(0xffffffffu, p4, off);
                q0 += __shfl_xor_sync(0xffffffffu, q0, off);
                q1 += __shfl_xor_sync(0xffffffffu, q1, off);
                q2 += __shfl_xor_sync(0xffffffffu, q2, off);
                q3 += __shfl_xor_sync(0xffffffffu, q3, off);
                q4 += __shfl_xor_sync(0xffffffffu, q4, off);
            }
            if (q == 0) {
                g_P[r][i][o][0] = p0;  g_P[r][i][o][1] = p1;
                g_P[r][i][o][2] = p2;  g_P[r][i][o][3] = p3;
                g_PV[r][i][o]   = p4;
                if (do_b) {
                    g_Pb[r][o][0] = q0;  g_Pb[r][o][1] = q1;
                    g_Pb[r][o][2] = q2;  g_Pb[r][o][3] = q3;
                    g_PVb[r][o]   = q4;
                }
            }
        }
    } else if (blk < NPBLK + nMean) {
        // ---- plane means ----
        int m     = blk - NPBLK;
        int plane = m >> 4;           // b*4 + ch   (NCH=16)
        int chunk = m & (NCH - 1);
        int b  = plane >> 2;
        int ch = plane & 3;
        const float* src = (ch < 3) ? (rgb + ((size_t)b * 3 + ch) * HW)
                                    : (edge + (size_t)b * HW);
        const float4* s4 = (const float4*)(src) + chunk * (HW / NCH / 4);

        float s = 0.0f;
        #pragma unroll
        for (int k = 0; k < HW / NCH / 4 / 256; k++) {      // 4 float4 in flight
            float4 v = s4[k * 256 + t];
            s += (v.x + v.y) + (v.z + v.w);
        }
        #pragma unroll
        for (int off = 16; off > 0; off >>= 1)
            s += __shfl_xor_sync(0xffffffffu, s, off);
        __shared__ float red[8];
        if ((t & 31) == 0) red[t >> 5] = s;
        __syncthreads();
        if (t == 0) {
            float tt = 0.f;
            #pragma unroll
            for (int w = 0; w < 8; w++) tt += red[w];
            g_part[plane][chunk] = tt;
        }
    } else {
        // ---- fused guide, warp-parallel: warp j -> output row j ----
        int j = t >> 5;              // 0..7
        int l = t & 31;
        const float* wg = Wg + (size_t)j * CMID;
        float a0 = 0.f, a1 = 0.f, a2 = 0.f, a3 = 0.f, vb = 0.f;
        #pragma unroll
        for (int hh = 0; hh < 2; hh++) {
            int c = hh * 32 + l;
            float w = wg[c];
            float4 w1v = *(const float4*)(W1 + c * 4);
            a0 += w * w1v.x;  a1 += w * w1v.y;
            a2 += w * w1v.z;  a3 += w * w1v.w;
            vb += w * b1[c];
        }
        #pragma unroll
        for (int off = 16; off > 0; off >>= 1) {
            a0 += __shfl_xor_sync(0xffffffffu, a0, off);
            a1 += __shfl_xor_sync(0xffffffffu, a1, off);
            a2 += __shfl_xor_sync(0xffffffffu, a2, off);
            a3 += __shfl_xor_sync(0xffffffffu, a3, off);
            vb += __shfl_xor_sync(0xffffffffu, vb, off);
        }
        if (l == 0) {
            g_G[j][0] = a0; g_G[j][1] = a1; g_G[j][2] = a2; g_G[j][3] = a3;
            g_gb[j]   = vb + bg[j];
        }
    }
}

// =====================================================================
// Kernel B: per-(b,r) fold of P with the batch sigmoid gates -> g_Mt/g_V.
// grid = B*RNUM blocks x 256 threads; gate dot products warp-parallel.
// =====================================================================
__global__ void __launch_bounds__(256)
k_B(const float* __restrict__ W1,  const float* __restrict__ b1,
    const float* __restrict__ Wk1, const float* __restrict__ bk1)
{
    int b = blockIdx.x >> 3;
    int r = blockIdx.x & 7;
    int t = threadIdx.x;

    __shared__ float xm[4];
    __shared__ float gsh[CMID];
    __shared__ float tgs[RNUM];

    if (t < 4) {
        float s = 0.f;
        #pragma unroll
        for (int j = 0; j < NCH; j++) s += g_part[b * 4 + t][j];
        xm[t] = s * (1.0f / (float)HW);
    }
    __syncthreads();

    if (t < CMID) {
        float4 w = *(const float4*)(W1 + t * 4);
        gsh[t] = b1[t] + w.x * xm[0] + w.y * xm[1] + w.z * xm[2] + w.w * xm[3];
    }
    __syncthreads();

    // warp w computes gate row j = r*8 + w (lanes split the 64-c dot)
    {
        int w = t >> 5;              // 0..7
        int l = t & 31;
        int j = r * RNUM + w;
        const float* wk = Wk1 + (size_t)j * CMID;
        float s = gsh[l] * wk[l] + gsh[l + 32] * wk[l + 32];
        #pragma unroll
        for (int off = 16; off > 0; off >>= 1)
            s += __shfl_xor_sync(0xffffffffu, s, off);
        if (l == 0)
            tgs[w] = 1.0f / (1.0f + expf(-(s + bk1[j])));
    }
    __syncthreads();

    {
        int o = t & 63;
        int j = t >> 6;          // 0..3
        float acc = g_Pb[r][o][j];
        #pragma unroll
        for (int i = 0; i < RNUM; i++)
            acc += tgs[i] * g_P[r][i][o][j];
        g_Mt[b][r][j][o] = acc;
        if (t < 64) {
            float av = g_PVb[r][o];
            #pragma unroll
            for (int i = 0; i < RNUM; i++)
                av += tgs[i] * g_PV[r][i][o];
            g_V[b][r][o] = av;
        }
    }
}

// =====================================================================
// Kernel M: 256 threads, 2 pixels/thread, float2 I/O, grid = B*128.
// __launch_bounds__(256,3) caps regs at 85 -> 3 blocks (24 warps)/SM.
//   smem Ms: region stride 260 floats (slot = 65r + k, injective mod 32)
//   smem Vs: region stride 68  floats (slot = 17r + k, injective mod 32)
// =====================================================================
__global__ void __launch_bounds__(256, 3)
k_M(const float* __restrict__ rgb,
    const float* __restrict__ edge,
    float* __restrict__ out)
{
    __shared__ __align__(16) float Ms[RNUM * 260];
    __shared__ __align__(16) float Vs[RNUM * 68];
    __shared__ float4 Gs[RNUM];
    __shared__ float  gbs[RNUM];

    int b = blockIdx.x >> 7;           // 128 blocks per batch image
    int t = threadIdx.x;

    // ---- issue input loads first (independent of staging) ----
    int idx = ((blockIdx.x & 127) << 8) + t;      // float2 index within plane
    const float2* rp2 = (const float2*)(rgb + (size_t)b * 3 * HW);
    const float2* ep2 = (const float2*)(edge + (size_t)b * HW);
    float2 xv0 = rp2[idx];
    float2 xv1 = rp2[HW / 2 + idx];
    float2 xv2 = rp2[2 * (HW / 2) + idx];
    float2 xv3 = ep2[idx];

    // ---- stage fused per-batch tables ----
    const float* Mg = &g_Mt[b][0][0][0];          // 2048 contiguous floats
    #pragma unroll
    for (int k0 = 0; k0 < RNUM * CMID * 4; k0 += 256) {
        int k = k0 + t;
        Ms[(k >> 8) * 260 + (k & 255)] = Mg[k];
    }
    const float* Vg = &g_V[b][0][0];              // 512 contiguous floats
    #pragma unroll
    for (int k0 = 0; k0 < RNUM * CMID; k0 += 256) {
        int k = k0 + t;
        Vs[(k >> 6) * 68 + (k & 63)] = Vg[k];
    }
    if (t < RNUM) {
        Gs[t]  = *(const float4*)&g_G[t][0];
        gbs[t] = g_gb[t];
    }
    __syncthreads();

    float xs[2][4];
    xs[0][0]=xv0.x; xs[1][0]=xv0.y;
    xs[0][1]=xv1.x; xs[1][1]=xv1.y;
    xs[0][2]=xv2.x; xs[1][2]=xv2.y;
    xs[0][3]=xv3.x; xs[1][3]=xv3.y;

    const float* Mr[2];
    const float* Vr[2];
    #pragma unroll
    for (int j = 0; j < 2; j++) {
        float4 G0 = Gs[0];
        float best = gbs[0] + G0.x*xs[j][0] + G0.y*xs[j][1]
                            + G0.z*xs[j][2] + G0.w*xs[j][3];
        int br = 0;
        #pragma unroll
        for (int r = 1; r < RNUM; r++) {
            float4 Gr = Gs[r];
            float gv = gbs[r] + Gr.x*xs[j][0] + Gr.y*xs[j][1]
                              + Gr.z*xs[j][2] + Gr.w*xs[j][3];
            if (gv > best) { best = gv; br = r; }
        }
        Mr[j] = &Ms[br * 260];
        Vr[j] = &Vs[br * 68];
    }

    unsigned long long xb[2][4];
    #pragma unroll
    for (int j = 0; j < 2; j++)
        #pragma unroll
        for (int i = 0; i < 4; i++)
            xb[j][i] = pack2(xs[j][i]);

    float* op = out + (size_t)b * CMID * HW + (size_t)idx * 2;

    #pragma unroll 8
    for (int o4 = 0; o4 < 16; o4++) {
        float ov[4][2];                            // [cc][px]
        #pragma unroll
        for (int j = 0; j < 2; j++) {
            ulonglong2 vv = *(const ulonglong2*)(Vr[j] + o4 * 4);
            unsigned long long r0 = vv.x, r1 = vv.y;
            #pragma unroll
            for (int i = 0; i < 4; i++) {
                ulonglong2 m = *(const ulonglong2*)(Mr[j] + i * 64 + o4 * 4);
                r0 = fma2(m.x, xb[j][i], r0);
                r1 = fma2(m.y, xb[j][i], r1);
            }
            unpack2(r0, ov[0][j], ov[1][j]);
            unpack2(r1, ov[2][j], ov[3][j]);
        }
        #pragma unroll
        for (int cc = 0; cc < 4; cc++) {
            float2 s = make_float2(ov[cc][0], ov[cc][1]);
            *(float2*)(op + (size_t)(o4 * 4 + cc) * HW) = s;
        }
    }
}

// =====================================================================
extern "C" void kernel_launch(void* const* d_in, const int* in_sizes, int n_in,
                              void* d_out, int out_size)
{
    const float* rgb  = (const float*)d_in[0];
    const float* edge = (const float*)d_in[1];
    const float* W1   = (const float*)d_in[2];
    const float* b1   = (const float*)d_in[3];
    const float* Wk1  = (const float*)d_in[4];
    const float* bk1  = (const float*)d_in[5];
    const float* Wk2  = (const float*)d_in[6];
    const float* bk2  = (const float*)d_in[7];
    const float* Wg   = (const float*)d_in[8];
    const float* bg   = (const float*)d_in[9];
    float* out = (float*)d_out;

    int B = in_sizes[1] / HW;      // edge is (B,1,H,W)
    if (B < 1) B = 1;
    if (B > MAXB) B = MAXB;

    int nMean = 4 * B * NCH;
    k_A<<<NPBLK + nMean + 1, 256>>>(rgb, edge, W1, b1, Wk2, bk2, Wg, bg, nMean);
    k_B<<<B * RNUM, 256>>>(W1, b1, Wk1, bk1);
    k_M<<<B * 128, 256>>>(rgb, edge, out);
}

// round 15
// speedup vs baseline: 1.0829x; 1.0829x over previous
#include <cuda_runtime.h>
#include <math.h>

// Problem constants (fixed by the dataset: B=4, H=W=256, C=64, r=8)
#define HW      65536
#define CMID    64
#define RNUM    8
#define MAXB    4
#define NCH     16   // mean-reduction chunks per plane
#define NPBLK   64   // P-contraction blocks (each: one r, 8 o's)

// -------- device scratch (no allocations allowed) --------
__device__ float g_part[MAXB * 4][NCH];        // partial plane sums
__device__ float g_P  [RNUM][RNUM][CMID][4];   // P[r][i][o][j] = sum_c Wk2[r][o*C+c][i] * W1[c][j]
__device__ float g_PV [RNUM][RNUM][CMID];      // same contracted with b1
__device__ float g_Pb [RNUM][CMID][4];         // bk2 folded with W1
__device__ float g_PVb[RNUM][CMID];            // bk2 folded with b1
__device__ float g_Mt [MAXB][RNUM][4][CMID];   // final fused kernel (transposed)
__device__ float g_V  [MAXB][RNUM][CMID];      // final fused bias
__device__ float g_G[RNUM][4];                 // fused guide: Wg @ W1
__device__ float g_gb[RNUM];                   // fused guide bias

// ---------------- packed f32x2 helpers ----------------
__device__ __forceinline__ unsigned long long fma2(unsigned long long a,
                                                   unsigned long long b,
                                                   unsigned long long c)
{
    unsigned long long d;
    asm("fma.rn.f32x2 %0, %1, %2, %3;" : "=l"(d) : "l"(a), "l"(b), "l"(c));
    return d;
}
__device__ __forceinline__ unsigned long long pack2(float x)
{
    unsigned long long d;
    unsigned int u = __float_as_uint(x);
    asm("mov.b64 %0, {%1, %1};" : "=l"(d) : "r"(u));
    return d;
}
__device__ __forceinline__ void unpack2(unsigned long long v, float& lo, float& hi)
{
    unsigned int a, b;
    asm("mov.b64 {%0, %1}, %2;" : "=r"(a), "=r"(b) : "l"(v));
    lo = __uint_as_float(a);
    hi = __uint_as_float(b);
}

// =====================================================================
// Kernel A (256 threads/block): independent roles per block.
//  [0, NPBLK)           : P contraction — ALL 256 threads, conflict-free
//                         interleaved-c smem reads, 16-iteration loop.
//  [NPBLK, NPBLK+nMean) : plane-mean partial sums (NCH=16 -> 256 blocks)
//  last                 : fused guide (warp-parallel)
// =====================================================================
__global__ void __launch_bounds__(256)
k_A(const float* __restrict__ rgb,  const float* __restrict__ edge,
    const float* __restrict__ W1,   const float* __restrict__ b1,
    const float* __restrict__ Wk2,  const float* __restrict__ bk2,
    const float* __restrict__ Wg,   const float* __restrict__ bg,
    int nMean)
{
    int blk = blockIdx.x;
    int t   = threadIdx.x;

    if (blk < NPBLK) {
        // ---- P contraction: r = blk>>3, og = blk&7 (o in [og*8, og*8+8)) ----
        __shared__ float w2s[8 * CMID * 8];   // [oi][c][i] flat, 16 KB
        __shared__ float bks[8 * CMID];       // [oi][c],      2 KB
        __shared__ float w1s[CMID * 4];
        __shared__ float b1s[CMID];

        int r  = blk >> 3, og = blk & 7;

        {
            const float4* src = (const float4*)(Wk2 + (size_t)r * 32768 + og * 4096);
            float4* dst = (float4*)w2s;
            #pragma unroll
            for (int k = 0; k < 4; k++)                 // 1024 float4
                dst[k * 256 + t] = src[k * 256 + t];
            const float4* srcb = (const float4*)(bk2 + (size_t)r * 4096 + og * 512);
            if (t < 128) ((float4*)bks)[t] = srcb[t];   // 128 float4
            if (t >= 128 && t < 192) ((float4*)w1s)[t - 128] = ((const float4*)W1)[t - 128];
            if (t >= 192 && t < 208) ((float4*)b1s)[t - 192] = ((const float4*)b1)[t - 192];
        }
        __syncthreads();

        {
            // thread = (oi, i, q): q = c-quarter, c interleaved as cc*4+q
            int q  = t & 3;              // 0..3
            int i  = (t >> 2) & 7;       // 0..7
            int oi = t >> 5;             // 0..7
            int o  = og * 8 + oi;

            float p0 = 0.f, p1 = 0.f, p2 = 0.f, p3 = 0.f, p4 = 0.f;
            float q0 = 0.f, q1 = 0.f, q2 = 0.f, q3 = 0.f, q4 = 0.f;
            const bool do_b = (i == 0);
            const float* wrow = &w2s[oi * (CMID * 8) + i];
            const float* brow = &bks[oi * CMID];

            #pragma unroll
            for (int cc = 0; cc < 16; cc++) {
                int c = cc * 4 + q;      // banks 8q+i: conflict-free
                float kv = wrow[c * 8];
                float4 w = *(const float4*)(w1s + c * 4);
                float  bb = b1s[c];
                p0 += kv * w.x;  p1 += kv * w.y;  p2 += kv * w.z;  p3 += kv * w.w;
                p4 += kv * bb;
                if (do_b) {
                    float bz = brow[c];
                    q0 += bz * w.x;  q1 += bz * w.y;  q2 += bz * w.z;  q3 += bz * w.w;
                    q4 += bz * bb;
                }
            }
            #pragma unroll
            for (int off = 1; off < 4; off <<= 1) {
                p0 += __shfl_xor_sync(0xffffffffu, p0, off);
                p1 += __shfl_xor_sync(0xffffffffu, p1, off);
                p2 += __shfl_xor_sync(0xffffffffu, p2, off);
                p3 += __shfl_xor_sync(0xffffffffu, p3, off);
                p4 += __shfl_xor_sync(0xffffffffu, p4, off);
                q0 += __shfl_xor_sync(0xffffffffu, q0, off);
                q1 += __shfl_xor_sync(0xffffffffu, q1, off);
                q2 += __shfl_xor_sync(0xffffffffu, q2, off);
                q3 += __shfl_xor_sync(0xffffffffu, q3, off);
                q4 += __shfl_xor_sync(0xffffffffu, q4, off);
            }
            if (q == 0) {
                g_P[r][i][o][0] = p0;  g_P[r][i][o][1] = p1;
                g_P[r][i][o][2] = p2;  g_P[r][i][o][3] = p3;
                g_PV[r][i][o]   = p4;
                if (do_b) {
                    g_Pb[r][o][0] = q0;  g_Pb[r][o][1] = q1;
                    g_Pb[r][o][2] = q2;  g_Pb[r][o][3] = q3;
                    g_PVb[r][o]   = q4;
                }
            }
        }
    } else if (blk < NPBLK + nMean) {
        // ---- plane means ----
        int m     = blk - NPBLK;
        int plane = m >> 4;           // b*4 + ch   (NCH=16)
        int chunk = m & (NCH - 1);
        int b  = plane >> 2;
        int ch = plane & 3;
        const float* src = (ch < 3) ? (rgb + ((size_t)b * 3 + ch) * HW)
                                    : (edge + (size_t)b * HW);
        const float4* s4 = (const float4*)(src) + chunk * (HW / NCH / 4);

        float s = 0.0f;
        #pragma unroll
        for (int k = 0; k < HW / NCH / 4 / 256; k++) {      // 4 float4 in flight
            float4 v = s4[k * 256 + t];
            s += (v.x + v.y) + (v.z + v.w);
        }
        #pragma unroll
        for (int off = 16; off > 0; off >>= 1)
            s += __shfl_xor_sync(0xffffffffu, s, off);
        __shared__ float red[8];
        if ((t & 31) == 0) red[t >> 5] = s;
        __syncthreads();
        if (t == 0) {
            float tt = 0.f;
            #pragma unroll
            for (int w = 0; w < 8; w++) tt += red[w];
            g_part[plane][chunk] = tt;
        }
    } else {
        // ---- fused guide, warp-parallel: warp j -> output row j ----
        int j = t >> 5;              // 0..7
        int l = t & 31;
        const float* wg = Wg + (size_t)j * CMID;
        float a0 = 0.f, a1 = 0.f, a2 = 0.f, a3 = 0.f, vb = 0.f;
        #pragma unroll
        for (int hh = 0; hh < 2; hh++) {
            int c = hh * 32 + l;
            float w = wg[c];
            float4 w1v = *(const float4*)(W1 + c * 4);
            a0 += w * w1v.x;  a1 += w * w1v.y;
            a2 += w * w1v.z;  a3 += w * w1v.w;
            vb += w * b1[c];
        }
        #pragma unroll
        for (int off = 16; off > 0; off >>= 1) {
            a0 += __shfl_xor_sync(0xffffffffu, a0, off);
            a1 += __shfl_xor_sync(0xffffffffu, a1, off);
            a2 += __shfl_xor_sync(0xffffffffu, a2, off);
            a3 += __shfl_xor_sync(0xffffffffu, a3, off);
            vb += __shfl_xor_sync(0xffffffffu, vb, off);
        }
        if (l == 0) {
            g_G[j][0] = a0; g_G[j][1] = a1; g_G[j][2] = a2; g_G[j][3] = a3;
            g_gb[j]   = vb + bg[j];
        }
    }
}

// =====================================================================
// Kernel B: per-(b,r) fold of P with the batch sigmoid gates -> g_Mt/g_V.
// grid = B*RNUM blocks x 256 threads; gate dot products warp-parallel.
// =====================================================================
__global__ void __launch_bounds__(256)
k_B(const float* __restrict__ W1,  const float* __restrict__ b1,
    const float* __restrict__ Wk1, const float* __restrict__ bk1)
{
    int b = blockIdx.x >> 3;
    int r = blockIdx.x & 7;
    int t = threadIdx.x;

    __shared__ float xm[4];
    __shared__ float gsh[CMID];
    __shared__ float tgs[RNUM];

    if (t < 4) {
        float s = 0.f;
        #pragma unroll
        for (int j = 0; j < NCH; j++) s += g_part[b * 4 + t][j];
        xm[t] = s * (1.0f / (float)HW);
    }
    __syncthreads();

    if (t < CMID) {
        float4 w = *(const float4*)(W1 + t * 4);
        gsh[t] = b1[t] + w.x * xm[0] + w.y * xm[1] + w.z * xm[2] + w.w * xm[3];
    }
    __syncthreads();

    // warp w computes gate row j = r*8 + w (lanes split the 64-c dot)
    {
        int w = t >> 5;              // 0..7
        int l = t & 31;
        int j = r * RNUM + w;
        const float* wk = Wk1 + (size_t)j * CMID;
        float s = gsh[l] * wk[l] + gsh[l + 32] * wk[l + 32];
        #pragma unroll
        for (int off = 16; off > 0; off >>= 1)
            s += __shfl_xor_sync(0xffffffffu, s, off);
        if (l == 0)
            tgs[w] = 1.0f / (1.0f + expf(-(s + bk1[j])));
    }
    __syncthreads();

    {
        int o = t & 63;
        int j = t >> 6;          // 0..3
        float acc = g_Pb[r][o][j];
        #pragma unroll
        for (int i = 0; i < RNUM; i++)
            acc += tgs[i] * g_P[r][i][o][j];
        g_Mt[b][r][j][o] = acc;
        if (t < 64) {
            float av = g_PVb[r][o];
            #pragma unroll
            for (int i = 0; i < RNUM; i++)
                av += tgs[i] * g_PV[r][i][o];
            g_V[b][r][o] = av;
        }
    }
}

// =====================================================================
// Kernel M: 256 threads, 2 pixels/thread, float2 I/O, grid = B*128.
// Plain launch bounds (no min-blocks cap: 86 regs, no spills).
// Input LDGs issued BEFORE smem staging so DRAM latency hides behind it.
//   smem Ms: region stride 260 floats (slot = 65r + k, injective mod 32)
//   smem Vs: region stride 68  floats (slot = 17r + k, injective mod 32)
// =====================================================================
__global__ void __launch_bounds__(256)
k_M(const float* __restrict__ rgb,
    const float* __restrict__ edge,
    float* __restrict__ out)
{
    __shared__ __align__(16) float Ms[RNUM * 260];
    __shared__ __align__(16) float Vs[RNUM * 68];
    __shared__ float4 Gs[RNUM];
    __shared__ float  gbs[RNUM];

    int b = blockIdx.x >> 7;           // 128 blocks per batch image
    int t = threadIdx.x;

    // ---- issue input loads first (independent of staging) ----
    int idx = ((blockIdx.x & 127) << 8) + t;      // float2 index within plane
    const float2* rp2 = (const float2*)(rgb + (size_t)b * 3 * HW);
    const float2* ep2 = (const float2*)(edge + (size_t)b * HW);
    float2 xv0 = rp2[idx];
    float2 xv1 = rp2[HW / 2 + idx];
    float2 xv2 = rp2[2 * (HW / 2) + idx];
    float2 xv3 = ep2[idx];

    // ---- stage fused per-batch tables ----
    const float* Mg = &g_Mt[b][0][0][0];          // 2048 contiguous floats
    #pragma unroll
    for (int k0 = 0; k0 < RNUM * CMID * 4; k0 += 256) {
        int k = k0 + t;
        Ms[(k >> 8) * 260 + (k & 255)] = Mg[k];
    }
    const float* Vg = &g_V[b][0][0];              // 512 contiguous floats
    #pragma unroll
    for (int k0 = 0; k0 < RNUM * CMID; k0 += 256) {
        int k = k0 + t;
        Vs[(k >> 6) * 68 + (k & 63)] = Vg[k];
    }
    if (t < RNUM) {
        Gs[t]  = *(const float4*)&g_G[t][0];
        gbs[t] = g_gb[t];
    }
    __syncthreads();

    float xs[2][4];
    xs[0][0]=xv0.x; xs[1][0]=xv0.y;
    xs[0][1]=xv1.x; xs[1][1]=xv1.y;
    xs[0][2]=xv2.x; xs[1][2]=xv2.y;
    xs[0][3]=xv3.x; xs[1][3]=xv3.y;

    const float* Mr[2];
    const float* Vr[2];
    #pragma unroll
    for (int j = 0; j < 2; j++) {
        float4 G0 = Gs[0];
        float best = gbs[0] + G0.x*xs[j][0] + G0.y*xs[j][1]
                            + G0.z*xs[j][2] + G0.w*xs[j][3];
        int br = 0;
        #pragma unroll
        for (int r = 1; r < RNUM; r++) {
            float4 Gr = Gs[r];
            float gv = gbs[r] + Gr.x*xs[j][0] + Gr.y*xs[j][1]
                              + Gr.z*xs[j][2] + Gr.w*xs[j][3];
            if (gv > best) { best = gv; br = r; }
        }
        Mr[j] = &Ms[br * 260];
        Vr[j] = &Vs[br * 68];
    }

    unsigned long long xb[2][4];
    #pragma unroll
    for (int j = 0; j < 2; j++)
        #pragma unroll
        for (int i = 0; i < 4; i++)
            xb[j][i] = pack2(xs[j][i]);

    float* op = out + (size_t)b * CMID * HW + (size_t)idx * 2;

    #pragma unroll 8
    for (int o4 = 0; o4 < 16; o4++) {
        float ov[4][2];                            // [cc][px]
        #pragma unroll
        for (int j = 0; j < 2; j++) {
            ulonglong2 vv = *(const ulonglong2*)(Vr[j] + o4 * 4);
            unsigned long long r0 = vv.x, r1 = vv.y;
            #pragma unroll
            for (int i = 0; i < 4; i++) {
                ulonglong2 m = *(const ulonglong2*)(Mr[j] + i * 64 + o4 * 4);
                r0 = fma2(m.x, xb[j][i], r0);
                r1 = fma2(m.y, xb[j][i], r1);
            }
            unpack2(r0, ov[0][j], ov[1][j]);
            unpack2(r1, ov[2][j], ov[3][j]);
        }
        #pragma unroll
        for (int cc = 0; cc < 4; cc++) {
            float2 s = make_float2(ov[cc][0], ov[cc][1]);
            *(float2*)(op + (size_t)(o4 * 4 + cc) * HW) = s;
        }
    }
}

// =====================================================================
extern "C" void kernel_launch(void* const* d_in, const int* in_sizes, int n_in,
                              void* d_out, int out_size)
{
    const float* rgb  = (const float*)d_in[0];
    const float* edge = (const float*)d_in[1];
    const float* W1   = (const float*)d_in[2];
    const float* b1   = (const float*)d_in[3];
    const float* Wk1  = (const float*)d_in[4];
    const float* bk1  = (const float*)d_in[5];
    const float* Wk2  = (const float*)d_in[6];
    const float* bk2  = (const float*)d_in[7];
    const float* Wg   = (const float*)d_in[8];
    const float* bg   = (const float*)d_in[9];
    float* out = (float*)d_out;

    int B = in_sizes[1] / HW;      // edge is (B,1,H,W)
    if (B < 1) B = 1;
    if (B > MAXB) B = MAXB;

    int nMean = 4 * B * NCH;
    k_A<<<NPBLK + nMean + 1, 256>>>(rgb, edge, W1, b1, Wk2, bk2, Wg, bg, nMean);
    k_B<<<B * RNUM, 256>>>(W1, b1, Wk1, bk1);
    k_M<<<B * 128, 256>>>(rgb, edge, out);
}

// round 16
// speedup vs baseline: 1.2962x; 1.1969x over previous
#include <cuda_runtime.h>
#include <cuda_fp16.h>
#include <math.h>

// Problem constants (fixed by the dataset: B=4, H=W=256, C=64, r=8)
#define HW      65536
#define CMID    64
#define RNUM    8
#define MAXB    4
#define NCH     16   // mean-reduction chunks per plane
#define NPBLK   64   // P-contraction blocks (each: one r, 8 o's)

// -------- device scratch (no allocations allowed) --------
__device__ float g_part[MAXB * 4][NCH];        // partial plane sums
__device__ float g_P  [RNUM][RNUM][CMID][4];   // P[r][i][o][j] = sum_c Wk2[r][o*C+c][i] * W1[c][j]
__device__ float g_PV [RNUM][RNUM][CMID];      // same contracted with b1
__device__ float g_Pb [RNUM][CMID][4];         // bk2 folded with W1
__device__ float g_PVb[RNUM][CMID];            // bk2 folded with b1
__device__ __half g_Mth[MAXB][RNUM][4][CMID];  // final fused kernel (transposed, fp16)
__device__ float g_V  [MAXB][RNUM][CMID];      // final fused bias (fp32)
__device__ float g_G[RNUM][4];                 // fused guide: Wg @ W1
__device__ float g_gb[RNUM];                   // fused guide bias

// ---------------- packed f32x2 helpers ----------------
__device__ __forceinline__ unsigned long long fma2(unsigned long long a,
                                                   unsigned long long b,
                                                   unsigned long long c)
{
    unsigned long long d;
    asm("fma.rn.f32x2 %0, %1, %2, %3;" : "=l"(d) : "l"(a), "l"(b), "l"(c));
    return d;
}
__device__ __forceinline__ unsigned long long pack2(float x)
{
    unsigned long long d;
    unsigned int u = __float_as_uint(x);
    asm("mov.b64 %0, {%1, %1};" : "=l"(d) : "r"(u));
    return d;
}
__device__ __forceinline__ unsigned long long pkf2(float2 f)
{
    unsigned long long d;
    asm("mov.b64 %0, {%1, %2};" : "=l"(d)
        : "r"(__float_as_uint(f.x)), "r"(__float_as_uint(f.y)));
    return d;
}
__device__ __forceinline__ void unpack2(unsigned long long v, float& lo, float& hi)
{
    unsigned int a, b;
    asm("mov.b64 {%0, %1}, %2;" : "=r"(a), "=r"(b) : "l"(v));
    lo = __uint_as_float(a);
    hi = __uint_as_float(b);
}

// =====================================================================
// Kernel A (256 threads/block): independent roles per block.
//  [0, NPBLK)           : P contraction — ALL 256 threads, conflict-free
//  [NPBLK, NPBLK+nMean) : plane-mean partial sums (NCH=16)
//  last                 : fused guide (warp-parallel)
// =====================================================================
__global__ void __launch_bounds__(256)
k_A(const float* __restrict__ rgb,  const float* __restrict__ edge,
    const float* __restrict__ W1,   const float* __restrict__ b1,
    const float* __restrict__ Wk2,  const float* __restrict__ bk2,
    const float* __restrict__ Wg,   const float* __restrict__ bg,
    int nMean)
{
    int blk = blockIdx.x;
    int t   = threadIdx.x;

    if (blk < NPBLK) {
        __shared__ float w2s[8 * CMID * 8];   // [oi][c][i] flat, 16 KB
        __shared__ float bks[8 * CMID];       // [oi][c],      2 KB
        __shared__ float w1s[CMID * 4];
        __shared__ float b1s[CMID];

        int r  = blk >> 3, og = blk & 7;

        {
            const float4* src = (const float4*)(Wk2 + (size_t)r * 32768 + og * 4096);
            float4* dst = (float4*)w2s;
            #pragma unroll
            for (int k = 0; k < 4; k++)
                dst[k * 256 + t] = src[k * 256 + t];
            const float4* srcb = (const float4*)(bk2 + (size_t)r * 4096 + og * 512);
            if (t < 128) ((float4*)bks)[t] = srcb[t];
            if (t >= 128 && t < 192) ((float4*)w1s)[t - 128] = ((const float4*)W1)[t - 128];
            if (t >= 192 && t < 208) ((float4*)b1s)[t - 192] = ((const float4*)b1)[t - 192];
        }
        __syncthreads();

        {
            int q  = t & 3;              // c-quarter, c interleaved as cc*4+q
            int i  = (t >> 2) & 7;
            int oi = t >> 5;
            int o  = og * 8 + oi;

            float p0 = 0.f, p1 = 0.f, p2 = 0.f, p3 = 0.f, p4 = 0.f;
            float q0 = 0.f, q1 = 0.f, q2 = 0.f, q3 = 0.f, q4 = 0.f;
            const bool do_b = (i == 0);
            const float* wrow = &w2s[oi * (CMID * 8) + i];
            const float* brow = &bks[oi * CMID];

            #pragma unroll
            for (int cc = 0; cc < 16; cc++) {
                int c = cc * 4 + q;      // banks 8q+i: conflict-free
                float kv = wrow[c * 8];
                float4 w = *(const float4*)(w1s + c * 4);
                float  bb = b1s[c];
                p0 += kv * w.x;  p1 += kv * w.y;  p2 += kv * w.z;  p3 += kv * w.w;
                p4 += kv * bb;
                if (do_b) {
                    float bz = brow[c];
                    q0 += bz * w.x;  q1 += bz * w.y;  q2 += bz * w.z;  q3 += bz * w.w;
                    q4 += bz * bb;
                }
            }
            #pragma unroll
            for (int off = 1; off < 4; off <<= 1) {
                p0 += __shfl_xor_sync(0xffffffffu, p0, off);
                p1 += __shfl_xor_sync(0xffffffffu, p1, off);
                p2 += __shfl_xor_sync(0xffffffffu, p2, off);
                p3 += __shfl_xor_sync(0xffffffffu, p3, off);
                p4 += __shfl_xor_sync(0xffffffffu, p4, off);
                q0 += __shfl_xor_sync(0xffffffffu, q0, off);
                q1 += __shfl_xor_sync(0xffffffffu, q1, off);
                q2 += __shfl_xor_sync(0xffffffffu, q2, off);
                q3 += __shfl_xor_sync(0xffffffffu, q3, off);
                q4 += __shfl_xor_sync(0xffffffffu, q4, off);
            }
            if (q == 0) {
                g_P[r][i][o][0] = p0;  g_P[r][i][o][1] = p1;
                g_P[r][i][o][2] = p2;  g_P[r][i][o][3] = p3;
                g_PV[r][i][o]   = p4;
                if (do_b) {
                    g_Pb[r][o][0] = q0;  g_Pb[r][o][1] = q1;
                    g_Pb[r][o][2] = q2;  g_Pb[r][o][3] = q3;
                    g_PVb[r][o]   = q4;
                }
            }
        }
    } else if (blk < NPBLK + nMean) {
        int m     = blk - NPBLK;
        int plane = m >> 4;           // b*4 + ch   (NCH=16)
        int chunk = m & (NCH - 1);
        int b  = plane >> 2;
        int ch = plane & 3;
        const float* src = (ch < 3) ? (rgb + ((size_t)b * 3 + ch) * HW)
                                    : (edge + (size_t)b * HW);
        const float4* s4 = (const float4*)(src) + chunk * (HW / NCH / 4);

        float s = 0.0f;
        #pragma unroll
        for (int k = 0; k < HW / NCH / 4 / 256; k++) {
            float4 v = s4[k * 256 + t];
            s += (v.x + v.y) + (v.z + v.w);
        }
        #pragma unroll
        for (int off = 16; off > 0; off >>= 1)
            s += __shfl_xor_sync(0xffffffffu, s, off);
        __shared__ float red[8];
        if ((t & 31) == 0) red[t >> 5] = s;
        __syncthreads();
        if (t == 0) {
            float tt = 0.f;
            #pragma unroll
            for (int w = 0; w < 8; w++) tt += red[w];
            g_part[plane][chunk] = tt;
        }
    } else {
        int j = t >> 5;
        int l = t & 31;
        const float* wg = Wg + (size_t)j * CMID;
        float a0 = 0.f, a1 = 0.f, a2 = 0.f, a3 = 0.f, vb = 0.f;
        #pragma unroll
        for (int hh = 0; hh < 2; hh++) {
            int c = hh * 32 + l;
            float w = wg[c];
            float4 w1v = *(const float4*)(W1 + c * 4);
            a0 += w * w1v.x;  a1 += w * w1v.y;
            a2 += w * w1v.z;  a3 += w * w1v.w;
            vb += w * b1[c];
        }
        #pragma unroll
        for (int off = 16; off > 0; off >>= 1) {
            a0 += __shfl_xor_sync(0xffffffffu, a0, off);
            a1 += __shfl_xor_sync(0xffffffffu, a1, off);
            a2 += __shfl_xor_sync(0xffffffffu, a2, off);
            a3 += __shfl_xor_sync(0xffffffffu, a3, off);
            vb += __shfl_xor_sync(0xffffffffu, vb, off);
        }
        if (l == 0) {
            g_G[j][0] = a0; g_G[j][1] = a1; g_G[j][2] = a2; g_G[j][3] = a3;
            g_gb[j]   = vb + bg[j];
        }
    }
}

// =====================================================================
// Kernel B: per-(b,r) fold of P with the batch sigmoid gates.
// Writes g_Mth (fp16, round-to-nearest) and g_V (fp32).
// =====================================================================
__global__ void __launch_bounds__(256)
k_B(const float* __restrict__ W1,  const float* __restrict__ b1,
    const float* __restrict__ Wk1, const float* __restrict__ bk1)
{
    int b = blockIdx.x >> 3;
    int r = blockIdx.x & 7;
    int t = threadIdx.x;

    __shared__ float xm[4];
    __shared__ float gsh[CMID];
    __shared__ float tgs[RNUM];

    if (t < 4) {
        float s = 0.f;
        #pragma unroll
        for (int j = 0; j < NCH; j++) s += g_part[b * 4 + t][j];
        xm[t] = s * (1.0f / (float)HW);
    }
    __syncthreads();

    if (t < CMID) {
        float4 w = *(const float4*)(W1 + t * 4);
        gsh[t] = b1[t] + w.x * xm[0] + w.y * xm[1] + w.z * xm[2] + w.w * xm[3];
    }
    __syncthreads();

    {
        int w = t >> 5;
        int l = t & 31;
        int j = r * RNUM + w;
        const float* wk = Wk1 + (size_t)j * CMID;
        float s = gsh[l] * wk[l] + gsh[l + 32] * wk[l + 32];
        #pragma unroll
        for (int off = 16; off > 0; off >>= 1)
            s += __shfl_xor_sync(0xffffffffu, s, off);
        if (l == 0)
            tgs[w] = 1.0f / (1.0f + expf(-(s + bk1[j])));
    }
    __syncthreads();

    {
        int o = t & 63;
        int j = t >> 6;          // 0..3
        float acc = g_Pb[r][o][j];
        #pragma unroll
        for (int i = 0; i < RNUM; i++)
            acc += tgs[i] * g_P[r][i][o][j];
        g_Mth[b][r][j][o] = __float2half_rn(acc);
        if (t < 64) {
            float av = g_PVb[r][o];
            #pragma unroll
            for (int i = 0; i < RNUM; i++)
                av += tgs[i] * g_PV[r][i][o];
            g_V[b][r][o] = av;
        }
    }
}

// =====================================================================
// Kernel M: 256 threads, 2 pixels/thread, float2 I/O, grid = B*128.
// fp16 M table in smem (half LDS bytes), fp32 V + fp32 accumulation.
//   smem Mh: uint32(half2) array, region stride 130 slots
//            -> bank pair {2r, 2r+1} per region: conflict-free LDS.64
//   smem Vs: region stride 68 floats (slot = 17r + k, injective mod 32)
// =====================================================================
__global__ void __launch_bounds__(256)
k_M(const float* __restrict__ rgb,
    const float* __restrict__ edge,
    float* __restrict__ out)
{
    __shared__ __align__(16) unsigned int Mh[RNUM * 130]; // 4.16 KB
    __shared__ __align__(16) float Vs[RNUM * 68];
    __shared__ float4 Gs[RNUM];
    __shared__ float  gbs[RNUM];

    int b = blockIdx.x >> 7;           // 128 blocks per batch image
    int t = threadIdx.x;

    // ---- issue input loads first (independent of staging) ----
    int idx = ((blockIdx.x & 127) << 8) + t;      // float2 index within plane
    const float2* rp2 = (const float2*)(rgb + (size_t)b * 3 * HW);
    const float2* ep2 = (const float2*)(edge + (size_t)b * HW);
    float2 xv0 = rp2[idx];
    float2 xv1 = rp2[HW / 2 + idx];
    float2 xv2 = rp2[2 * (HW / 2) + idx];
    float2 xv3 = ep2[idx];

    // ---- stage fused per-batch tables ----
    {   // M (fp16): 1024 uint32 = 2048 halves, layout (k32>>7)*130 + (k32&127)
        const unsigned int* Mg = (const unsigned int*)&g_Mth[b][0][0][0];
        #pragma unroll
        for (int k0 = 0; k0 < 1024; k0 += 256) {
            int k = k0 + t;
            Mh[(k >> 7) * 130 + (k & 127)] = Mg[k];
        }
    }
    const float* Vg = &g_V[b][0][0];              // 512 contiguous floats
    #pragma unroll
    for (int k0 = 0; k0 < RNUM * CMID; k0 += 256) {
        int k = k0 + t;
        Vs[(k >> 6) * 68 + (k & 63)] = Vg[k];
    }
    if (t < RNUM) {
        Gs[t]  = *(const float4*)&g_G[t][0];
        gbs[t] = g_gb[t];
    }
    __syncthreads();

    float xs[2][4];
    xs[0][0]=xv0.x; xs[1][0]=xv0.y;
    xs[0][1]=xv1.x; xs[1][1]=xv1.y;
    xs[0][2]=xv2.x; xs[1][2]=xv2.y;
    xs[0][3]=xv3.x; xs[1][3]=xv3.y;

    const unsigned int* Mr[2];
    const float* Vr[2];
    #pragma unroll
    for (int j = 0; j < 2; j++) {
        float4 G0 = Gs[0];
        float best = gbs[0] + G0.x*xs[j][0] + G0.y*xs[j][1]
                            + G0.z*xs[j][2] + G0.w*xs[j][3];
        int br = 0;
        #pragma unroll
        for (int r = 1; r < RNUM; r++) {
            float4 Gr = Gs[r];
            float gv = gbs[r] + Gr.x*xs[j][0] + Gr.y*xs[j][1]
                              + Gr.z*xs[j][2] + Gr.w*xs[j][3];
            if (gv > best) { best = gv; br = r; }
        }
        Mr[j] = &Mh[br * 130];
        Vr[j] = &Vs[br * 68];
    }

    unsigned long long xb[2][4];
    #pragma unroll
    for (int j = 0; j < 2; j++)
        #pragma unroll
        for (int i = 0; i < 4; i++)
            xb[j][i] = pack2(xs[j][i]);

    float* op = out + (size_t)b * CMID * HW + (size_t)idx * 2;

    #pragma unroll 8
    for (int o4 = 0; o4 < 16; o4++) {
        float ov[4][2];                            // [cc][px]
        #pragma unroll
        for (int j = 0; j < 2; j++) {
            ulonglong2 vv = *(const ulonglong2*)(Vr[j] + o4 * 4);
            unsigned long long r0 = vv.x, r1 = vv.y;   // (V0,V1), (V2,V3) packed
            #pragma unroll
            for (int i = 0; i < 4; i++) {
                // 4 fp16 M coeffs (channels o4*4..o4*4+3) for input i
                uint2 m2 = *(const uint2*)(Mr[j] + i * 32 + o4 * 2);
                float2 f01 = __half22float2(*(const __half2*)&m2.x);
                float2 f23 = __half22float2(*(const __half2*)&m2.y);
                r0 = fma2(pkf2(f01), xb[j][i], r0);
                r1 = fma2(pkf2(f23), xb[j][i], r1);
            }
            unpack2(r0, ov[0][j], ov[1][j]);
            unpack2(r1, ov[2][j], ov[3][j]);
        }
        #pragma unroll
        for (int cc = 0; cc < 4; cc++) {
            float2 s = make_float2(ov[cc][0], ov[cc][1]);
            *(float2*)(op + (size_t)(o4 * 4 + cc) * HW) = s;
        }
    }
}

// =====================================================================
extern "C" void kernel_launch(void* const* d_in, const int* in_sizes, int n_in,
                              void* d_out, int out_size)
{
    const float* rgb  = (const float*)d_in[0];
    const float* edge = (const float*)d_in[1];
    const float* W1   = (const float*)d_in[2];
    const float* b1   = (const float*)d_in[3];
    const float* Wk1  = (const float*)d_in[4];
    const float* bk1  = (const float*)d_in[5];
    const float* Wk2  = (const float*)d_in[6];
    const float* bk2  = (const float*)d_in[7];
    const float* Wg   = (const float*)d_in[8];
    const float* bg   = (const float*)d_in[9];
    float* out = (float*)d_out;

    int B = in_sizes[1] / HW;      // edge is (B,1,H,W)
    if (B < 1) B = 1;
    if (B > MAXB) B = MAXB;

    int nMean = 4 * B * NCH;
    k_A<<<NPBLK + nMean + 1, 256>>>(rgb, edge, W1, b1, Wk2, bk2, Wg, bg, nMean);
    k_B<<<B * RNUM, 256>>>(W1, b1, Wk1, bk1);
    k_M<<<B * 128, 256>>>(rgb, edge, out);
}